// round 7
// baseline (speedup 1.0000x reference)
#include <cuda_runtime.h>

// Problem constants (fixed by dataset): B=1, N=4096, C=8, H=W=128, K=8
#define MAXN 8192
constexpr float RADIUS = 0.05f;
constexpr int H = 128, W = 128, C = 8, K = 8;
constexpr int TILE = 8;             // 8x8 pixel tiles
constexpr int TX = W / TILE;        // 16
constexpr int TY = H / TILE;        // 16
constexpr int NTILES = TX * TY;     // 256
constexpr int PIX = TILE * TILE;    // 64 pixels per tile
constexpr int SPLIT = 4;            // threads per pixel in scan phase
constexpr int TPB = PIX * SPLIT;    // 256 threads per block
constexpr int CAP = 512;            // per-tile bin capacity (measured max ~100)
constexpr int LISTN = PIX * SPLIT * K;

// Global scratch (no cudaMalloc allowed). g_cnt starts statically zero and is
// consumed-and-reset by render_kernel each invocation -> graph replays stay clean.
__device__ int    g_cnt[NTILES];
__device__ float4 g_bins[NTILES * CAP];   // (px, py, z, idx-as-float)

// Project + scatter each point into every tile whose pixel centers it can reach.
// Splat radius in pixels: RADIUS * (W/2) = 3.2; pad to 3.25 for fp safety.
__global__ void __launch_bounds__(256)
bin_kernel(const float* __restrict__ pts, int n) {
    int i = blockIdx.x * blockDim.x + threadIdx.x;
    if (i >= n) return;
    float x = pts[3 * i + 0];
    float y = pts[3 * i + 1];
    float z = pts[3 * i + 2];
    if (z <= 0.0f) return;
    float px = x / z;                       // exact IEEE, matches reference
    float py = y / z;
    float u = (px + 1.0f) * (0.5f * (float)W) - 0.5f;   // pixel ix center at u = ix
    float v = (py + 1.0f) * (0.5f * (float)H) - 0.5f;
    const float PR = 3.25f;
    int bx0 = max(0,      (int)floorf((u - PR) * (1.0f / TILE)));
    int bx1 = min(TX - 1, (int)floorf((u + PR) * (1.0f / TILE)));
    int by0 = max(0,      (int)floorf((v - PR) * (1.0f / TILE)));
    int by1 = min(TY - 1, (int)floorf((v + PR) * (1.0f / TILE)));
    if (bx0 > bx1 || by0 > by1) return;
    float4 rec = make_float4(px, py, z, __int_as_float(i));
    for (int by = by0; by <= by1; by++)
        for (int bx = bx0; bx <= bx1; bx++) {
            int t = by * TX + bx;
            int slot = atomicAdd(&g_cnt[t], 1);
            if (slot < CAP) g_bins[t * CAP + slot] = rec;
        }
}

__global__ void __launch_bounds__(TPB)
render_kernel(const float* __restrict__ feat, float* __restrict__ out) {
    __shared__ __align__(16) unsigned char raw[CAP * 16 + LISTN * 12];
    float4* s_cand = (float4*)raw;
    float*  s_mz   = (float*)(raw + CAP * 16);
    float*  s_md   = (float*)(raw + CAP * 16 + LISTN * 4);
    int*    s_mi   = (int*)  (raw + CAP * 16 + LISTN * 8);
    __shared__ int s_cnt;

    const int tile = blockIdx.x;
    const int tx = tile & (TX - 1);
    const int ty = tile >> 4;

    // consume-and-reset the tile count (keeps graph replays deterministic)
    if (threadIdx.x == 0) s_cnt = atomicExch(&g_cnt[tile], 0);
    __syncthreads();
    const int cnt = min(s_cnt, CAP);

    // stage candidates into smem (~52 -> one strided pass)
    for (int j = threadIdx.x; j < cnt; j += TPB)
        s_cand[j] = g_bins[tile * CAP + j];
    __syncthreads();

    const int p = threadIdx.x >> 2;        // pixel 0..63
    const int s = threadIdx.x & 3;         // sub-lane 0..3
    const int lx = p & (TILE - 1);
    const int ly = p >> 3;
    const int ix = tx * TILE + lx;
    const int iy = ty * TILE + ly;

    const float gx = ((float)ix + 0.5f) * (2.0f / W) - 1.0f;
    const float gy = ((float)iy + 0.5f) * (2.0f / H) - 1.0f;
    const float r2 = RADIUS * RADIUS;

    float lz[K], ld[K];
    int   li[K];
    #pragma unroll
    for (int k = 0; k < K; k++) { lz[k] = 3.0e38f; ld[k] = 0.0f; li[k] = 0; }

    for (int j = s; j < cnt; j += SPLIT) {
        float4 c = s_cand[j];
        float dx = gx - c.x;
        float dy = gy - c.y;
        float d2 = dx * dx + dy * dy;
        // distinct depths -> top-K set is order-independent (matches top_k)
        if (d2 < r2 && c.z < lz[K - 1]) {
            lz[K - 1] = c.z; ld[K - 1] = d2; li[K - 1] = __float_as_int(c.w);
            #pragma unroll
            for (int k = K - 1; k > 0; k--) {
                if (lz[k] < lz[k - 1]) {
                    float t0 = lz[k]; lz[k] = lz[k - 1]; lz[k - 1] = t0;
                    float t1 = ld[k]; ld[k] = ld[k - 1]; ld[k - 1] = t1;
                    int   t2 = li[k]; li[k] = li[k - 1]; li[k - 1] = t2;
                }
            }
        }
    }

    // publish local sorted top-8 lists
    {
        int off = (p * SPLIT + s) * K;
        #pragma unroll
        for (int k = 0; k < K; k++) {
            s_mz[off + k] = lz[k];
            s_md[off + k] = ld[k];
            s_mi[off + k] = li[k];
        }
    }
    __syncthreads();

    // 4-way merge + composite + store (one thread per pixel)
    if (s == 0) {
        int   hp[SPLIT];
        float hz[SPLIT];
        #pragma unroll
        for (int q = 0; q < SPLIT; q++) {
            hp[q] = (p * SPLIT + q) * K;
            hz[q] = s_mz[hp[q]];
        }

        float acc[C];
        #pragma unroll
        for (int c = 0; c < C; c++) acc[c] = 0.0f;
        float T = 1.0f;
        const float inv_r2 = 1.0f / r2;

        #pragma unroll
        for (int k = 0; k < K; k++) {
            int b = 0;
            if (hz[1] < hz[b]) b = 1;
            if (hz[2] < hz[b]) b = 2;
            if (hz[3] < hz[b]) b = 3;
            float zk = hz[b];
            if (zk < 1.0e38f) {
                float d2 = s_md[hp[b]];
                int   id = s_mi[hp[b]];
                float a = 1.0f - d2 * inv_r2;
                a = fminf(fmaxf(a, 0.0f), 1.0f);
                float w = a * T;
                const float4* f = (const float4*)(feat + (size_t)id * C);
                float4 f0 = __ldg(&f[0]);
                float4 f1 = __ldg(&f[1]);
                acc[0] += w * f0.x; acc[1] += w * f0.y;
                acc[2] += w * f0.z; acc[3] += w * f0.w;
                acc[4] += w * f1.x; acc[5] += w * f1.y;
                acc[6] += w * f1.z; acc[7] += w * f1.w;
                T *= (1.0f - a);
            }
            hp[b]++;
            hz[b] = ((hp[b] & (K - 1)) != 0) ? s_mz[hp[b]] : 3.0e38f;
        }

        float4* o = (float4*)(out + (size_t)(iy * W + ix) * C);
        o[0] = make_float4(acc[0], acc[1], acc[2], acc[3]);
        o[1] = make_float4(acc[4], acc[5], acc[6], acc[7]);
    }
}

extern "C" void kernel_launch(void* const* d_in, const int* in_sizes, int n_in,
                              void* d_out, int out_size) {
    const float* pts  = (const float*)d_in[0];   // [B,N,3] f32
    const float* feat = (const float*)d_in[1];   // [B,N,C] f32
    float* out = (float*)d_out;                  // [B,H,W,C] f32
    int n = in_sizes[0] / 3;                     // B=1 -> N
    if (n > MAXN) n = MAXN;

    bin_kernel<<<(n + 255) / 256, 256>>>(pts, n);
    render_kernel<<<NTILES, TPB>>>(feat, out);
}

// round 8
// speedup vs baseline: 1.1065x; 1.1065x over previous
#include <cuda_runtime.h>
#include <cstdint>

// Problem constants (fixed by dataset): B=1, N=4096, C=8, H=W=128, K=8
#define MAXN 8192
constexpr float RADIUS = 0.05f;
constexpr int H = 128, W = 128, C = 8, K = 8;
constexpr int TILE = 8;             // 8x8 pixel tiles
constexpr int TX = W / TILE;        // 16
constexpr int TY = H / TILE;        // 16
constexpr int NTILES = TX * TY;     // 256 CTAs
constexpr int PIX = TILE * TILE;    // 64 pixels per tile
constexpr int SPLIT = 4;            // threads per pixel in scan phase
constexpr int TPB = PIX * SPLIT;    // 256 threads per CTA
constexpr int CSIZE = 8;            // CTAs per cluster (4x2 tiles super-tile)
constexpr int SUPCAP = 192;         // per-CTA super-survivor cap (mean ~27)
constexpr int CAPT = 512;           // per-tile candidate cap (mean ~52)
constexpr int LISTN = PIX * SPLIT * K;   // 2048 merge-list entries

// ---- cluster / DSMEM helpers ----
__device__ __forceinline__ uint32_t cluster_rank() {
    uint32_t r; asm("mov.u32 %0, %%cluster_ctarank;" : "=r"(r)); return r;
}
__device__ __forceinline__ uint32_t smem_u32(const void* p) {
    return (uint32_t)__cvta_generic_to_shared(p);
}
__device__ __forceinline__ uint32_t mapa_u32(uint32_t addr, uint32_t rank) {
    uint32_t r;
    asm("mapa.shared::cluster.u32 %0, %1, %2;" : "=r"(r) : "r"(addr), "r"(rank));
    return r;
}
__device__ __forceinline__ int ld_cluster_i32(uint32_t addr) {
    int v; asm volatile("ld.shared::cluster.s32 %0, [%1];" : "=r"(v) : "r"(addr));
    return v;
}
__device__ __forceinline__ float4 ld_cluster_f4(uint32_t addr) {
    float4 v;
    asm volatile("ld.shared::cluster.v4.f32 {%0,%1,%2,%3}, [%4];"
                 : "=f"(v.x), "=f"(v.y), "=f"(v.z), "=f"(v.w) : "r"(addr));
    return v;
}
#define CLUSTER_ARRIVE() asm volatile("barrier.cluster.arrive.aligned;" ::: "memory")
#define CLUSTER_WAIT()   asm volatile("barrier.cluster.wait.aligned;" ::: "memory")

__global__ void __launch_bounds__(TPB) __cluster_dims__(CSIZE, 1, 1)
render_kernel(const float* __restrict__ pts,
              const float* __restrict__ feat,
              float* __restrict__ out, int n) {
    // smem: super-survivors | candidates | merge lists (+pad for benign overreads)
    __shared__ __align__(16) unsigned char raw[SUPCAP * 16 + CAPT * 16 + LISTN * 12 + 256];
    float4* s_sup  = (float4*)raw;
    float4* s_cand = (float4*)(raw + SUPCAP * 16);
    float*  s_mz   = (float*)(raw + SUPCAP * 16 + CAPT * 16);
    float*  s_md   = (float*)(raw + SUPCAP * 16 + CAPT * 16 + LISTN * 4);
    int*    s_mi   = (int*)  (raw + SUPCAP * 16 + CAPT * 16 + LISTN * 8);
    __shared__ int s_supcnt;
    __shared__ int s_cnt;

    const uint32_t rank = cluster_rank();
    // cluster c covers a 4x2 block of tiles; this CTA's tile within it:
    const int c  = blockIdx.x >> 3;
    const int cx = c & 3;               // 4 super-cols
    const int cy = c >> 2;              // 8 super-rows
    const int tx = cx * 4 + (rank & 3);
    const int ty = cy * 2 + (int)(rank >> 2);

    if (threadIdx.x == 0) { s_supcnt = 0; s_cnt = 0; }
    __syncthreads();

    // ---- super-tile bbox (32x16 px) over pixel centers, padded (NDC) ----
    const float SEPS = 1e-4f;
    const float SX0 = ((float)(cx * 32)      + 0.5f) * (2.0f / W) - 1.0f - RADIUS - SEPS;
    const float SX1 = ((float)(cx * 32 + 31) + 0.5f) * (2.0f / W) - 1.0f + RADIUS + SEPS;
    const float SY0 = ((float)(cy * 16)      + 0.5f) * (2.0f / H) - 1.0f - RADIUS - SEPS;
    const float SY1 = ((float)(cy * 16 + 15) + 0.5f) * (2.0f / H) - 1.0f + RADIUS + SEPS;

    // ---- Phase 1: this CTA culls its 1/8 slice of points vs super-bbox ----
    {
        const int slice = (n + CSIZE - 1) / CSIZE;
        const int i0 = (int)rank * slice;
        const int i1 = min(n, i0 + slice);
        for (int i = i0 + threadIdx.x; i < i1; i += TPB) {
            float x = pts[3 * i + 0];
            float y = pts[3 * i + 1];
            float z = pts[3 * i + 2];
            // division-free conservative test (z>0): x/z >= SX0 <=> x >= SX0*z
            bool hit = (z > 0.0f) &&
                       (x >= SX0 * z) && (x <= SX1 * z) &&
                       (y >= SY0 * z) && (y <= SY1 * z);
            if (hit) {
                float px = x / z;          // exact IEEE, matches reference
                float py = y / z;
                int slot = atomicAdd(&s_supcnt, 1);
                if (slot < SUPCAP)
                    s_sup[slot] = make_float4(px, py, z, __int_as_float(i));
            }
        }
    }
    __syncthreads();
    CLUSTER_ARRIVE(); CLUSTER_WAIT();      // all CTAs' survivor lists visible

    // ---- Phase 2: gather cluster survivors, refine vs this tile's bbox ----
    const float EPS = 1e-5f;
    const float x0 = ((float)(tx * TILE)            + 0.5f) * (2.0f / W) - 1.0f - RADIUS - EPS;
    const float x1 = ((float)(tx * TILE + TILE - 1) + 0.5f) * (2.0f / W) - 1.0f + RADIUS + EPS;
    const float y0 = ((float)(ty * TILE)            + 0.5f) * (2.0f / H) - 1.0f - RADIUS - EPS;
    const float y1 = ((float)(ty * TILE + TILE - 1) + 0.5f) * (2.0f / H) - 1.0f + RADIUS + EPS;

    {
        const uint32_t supcnt_a = smem_u32(&s_supcnt);
        const uint32_t sup_a    = smem_u32(s_sup);
        // prefetch all 8 peer counts (independent DSMEM loads, one latency round)
        int pc[CSIZE];
        #pragma unroll
        for (int q = 0; q < CSIZE; q++)
            pc[q] = min(ld_cluster_i32(mapa_u32(supcnt_a, q)), SUPCAP);
        #pragma unroll
        for (int q = 0; q < CSIZE; q++) {
            uint32_t base = mapa_u32(sup_a, q);
            for (int j = threadIdx.x; j < pc[q]; j += TPB) {
                float4 r = ld_cluster_f4(base + j * 16u);
                if (r.x >= x0 && r.x <= x1 && r.y >= y0 && r.y <= y1) {
                    int slot = atomicAdd(&s_cnt, 1);
                    if (slot < CAPT) s_cand[slot] = r;
                }
            }
        }
    }
    __syncthreads();
    CLUSTER_ARRIVE();                      // done reading peers (wait at kernel end)
    const int cnt = min(s_cnt, CAPT);

    // ---- Phase 3: split scan, 4 threads per pixel ----
    const int p = threadIdx.x >> 2;
    const int s = threadIdx.x & 3;
    const int lx = p & (TILE - 1);
    const int ly = p >> 3;
    const int ix = tx * TILE + lx;
    const int iy = ty * TILE + ly;

    const float gx = ((float)ix + 0.5f) * (2.0f / W) - 1.0f;
    const float gy = ((float)iy + 0.5f) * (2.0f / H) - 1.0f;
    const float r2 = RADIUS * RADIUS;

    float lz[K], ld[K];
    int   li[K];
    #pragma unroll
    for (int k = 0; k < K; k++) { lz[k] = 3.0e38f; ld[k] = 0.0f; li[k] = 0; }

    for (int j = s; j < cnt; j += SPLIT) {
        float4 cd = s_cand[j];
        float dx = gx - cd.x;
        float dy = gy - cd.y;
        float d2 = dx * dx + dy * dy;
        // distinct depths -> top-K set is order-independent (matches top_k)
        if (d2 < r2 && cd.z < lz[K - 1]) {
            lz[K - 1] = cd.z; ld[K - 1] = d2; li[K - 1] = __float_as_int(cd.w);
            #pragma unroll
            for (int k = K - 1; k > 0; k--) {
                if (lz[k] < lz[k - 1]) {
                    float t0 = lz[k]; lz[k] = lz[k - 1]; lz[k - 1] = t0;
                    float t1 = ld[k]; ld[k] = ld[k - 1]; ld[k - 1] = t1;
                    int   t2 = li[k]; li[k] = li[k - 1]; li[k - 1] = t2;
                }
            }
        }
    }

    {
        int off = (p * SPLIT + s) * K;
        #pragma unroll
        for (int k = 0; k < K; k++) {
            s_mz[off + k] = lz[k];
            s_md[off + k] = ld[k];
            s_mi[off + k] = li[k];
        }
    }
    __syncthreads();

    // ---- Phase 4: merge weights first, then batched feature gather ----
    if (s == 0) {
        int   hp[SPLIT];
        float hz[SPLIT];
        #pragma unroll
        for (int q = 0; q < SPLIT; q++) {
            hp[q] = (p * SPLIT + q) * K;
            hz[q] = s_mz[hp[q]];
        }

        float wk[K];
        int   idk[K];
        float T = 1.0f;
        const float inv_r2 = 1.0f / r2;

        #pragma unroll
        for (int k = 0; k < K; k++) {
            int b = 0;
            if (hz[1] < hz[b]) b = 1;
            if (hz[2] < hz[b]) b = 2;
            if (hz[3] < hz[b]) b = 3;
            bool valid = hz[b] < 1.0e38f;
            float d2 = s_md[hp[b]];            // benign garbage when !valid (pad)
            int   id = s_mi[hp[b]];
            float a = 1.0f - d2 * inv_r2;
            a = fminf(fmaxf(a, 0.0f), 1.0f);
            a = valid ? a : 0.0f;
            wk[k]  = a * T;
            idk[k] = valid ? id : 0;           // feat[0] * 0 -> harmless
            T *= (1.0f - a);
            hp[b]++;
            hz[b] = ((hp[b] & (K - 1)) != 0) ? s_mz[hp[b]] : 3.0e38f;
        }

        float acc[C];
        #pragma unroll
        for (int c2 = 0; c2 < C; c2++) acc[c2] = 0.0f;

        // two rounds of 4 independent feature-pair loads (MLP 8)
        #pragma unroll
        for (int half = 0; half < 2; half++) {
            float4 F0[4], F1[4];
            #pragma unroll
            for (int k = 0; k < 4; k++) {
                const float4* f = (const float4*)(feat + (size_t)idk[half * 4 + k] * C);
                F0[k] = __ldg(&f[0]);
                F1[k] = __ldg(&f[1]);
            }
            #pragma unroll
            for (int k = 0; k < 4; k++) {
                float w = wk[half * 4 + k];
                acc[0] += w * F0[k].x; acc[1] += w * F0[k].y;
                acc[2] += w * F0[k].z; acc[3] += w * F0[k].w;
                acc[4] += w * F1[k].x; acc[5] += w * F1[k].y;
                acc[6] += w * F1[k].z; acc[7] += w * F1[k].w;
            }
        }

        float4* o = (float4*)(out + (size_t)(iy * W + ix) * C);
        o[0] = make_float4(acc[0], acc[1], acc[2], acc[3]);
        o[1] = make_float4(acc[4], acc[5], acc[6], acc[7]);
    }

    CLUSTER_WAIT();   // no CTA exits while a peer may still read its smem
}

extern "C" void kernel_launch(void* const* d_in, const int* in_sizes, int n_in,
                              void* d_out, int out_size) {
    const float* pts  = (const float*)d_in[0];   // [B,N,3] f32
    const float* feat = (const float*)d_in[1];   // [B,N,C] f32
    float* out = (float*)d_out;                  // [B,H,W,C] f32
    int n = in_sizes[0] / 3;                     // B=1 -> N
    if (n > MAXN) n = MAXN;

    render_kernel<<<NTILES, TPB>>>(pts, feat, out, n);
}

// round 9
// speedup vs baseline: 1.2542x; 1.1335x over previous
#include <cuda_runtime.h>
#include <cstdint>

// Problem constants (fixed by dataset): B=1, N=4096, C=8, H=W=128, K=8
#define MAXN 8192
constexpr float RADIUS = 0.05f;
constexpr int H = 128, W = 128, C = 8, K = 8;
constexpr int TILE = 8;             // 8x8 pixel tiles
constexpr int TX = W / TILE;        // 16
constexpr int TY = H / TILE;        // 16
constexpr int NTILES = TX * TY;     // 256 CTAs
constexpr int PIX = TILE * TILE;    // 64 pixels per tile
constexpr int SPLIT = 8;            // threads per pixel in scan phase
constexpr int TPB = PIX * SPLIT;    // 512 threads per CTA
constexpr int CSIZE = 8;            // CTAs per cluster (4x2 tiles super-tile)
constexpr int SUPCAP = 192;         // per-CTA super-survivor cap (mean ~27)
constexpr int CAPT = 384;           // per-tile candidate cap (mean ~52)
constexpr int QCAP = 192;           // per-quadrant cap (mean ~27)
constexpr int PIXCAP = 40;          // per-pixel hit cap (mean ~8)

// ---- cluster / DSMEM helpers ----
__device__ __forceinline__ uint32_t cluster_rank() {
    uint32_t r; asm("mov.u32 %0, %%cluster_ctarank;" : "=r"(r)); return r;
}
__device__ __forceinline__ uint32_t smem_u32(const void* p) {
    return (uint32_t)__cvta_generic_to_shared(p);
}
__device__ __forceinline__ uint32_t mapa_u32(uint32_t addr, uint32_t rank) {
    uint32_t r;
    asm("mapa.shared::cluster.u32 %0, %1, %2;" : "=r"(r) : "r"(addr), "r"(rank));
    return r;
}
__device__ __forceinline__ int ld_cluster_i32(uint32_t addr) {
    int v; asm volatile("ld.shared::cluster.s32 %0, [%1];" : "=r"(v) : "r"(addr));
    return v;
}
__device__ __forceinline__ float4 ld_cluster_f4(uint32_t addr) {
    float4 v;
    asm volatile("ld.shared::cluster.v4.f32 {%0,%1,%2,%3}, [%4];"
                 : "=f"(v.x), "=f"(v.y), "=f"(v.z), "=f"(v.w) : "r"(addr));
    return v;
}
#define CLUSTER_ARRIVE() asm volatile("barrier.cluster.arrive.aligned;" ::: "memory")
#define CLUSTER_WAIT()   asm volatile("barrier.cluster.wait.aligned;" ::: "memory")

// smem layout (43008 B static, aliased across phases):
//   [    0,  3072)  s_sup   float4[192]          (dead after cluster pair 2)
//   [ 3072,  9216)  s_cand  float4[384]          (dead after quadrant build)
//   [    0, 10240)  s_hz    float[64*40]  ─┐ hit lists, alias sup/cand after
//   [10240, 20480)  s_hd    float[64*40]   ├ the pair-2 cluster wait
//   [20480, 30720)  s_hi    int  [64*40]  ─┘
//   [30720, 43008)  s_quad  float4[4][192]       (built from s_cand, read in scan)
constexpr int RAWSZ = 43008;

__global__ void __launch_bounds__(TPB) __cluster_dims__(CSIZE, 1, 1)
render_kernel(const float* __restrict__ pts,
              const float* __restrict__ feat,
              float* __restrict__ out, int n) {
    __shared__ __align__(16) unsigned char raw[RAWSZ];
    float4* s_sup  = (float4*)raw;
    float4* s_cand = (float4*)(raw + 3072);
    float*  s_hz   = (float*)raw;
    float*  s_hd   = (float*)(raw + 10240);
    int*    s_hi   = (int*)  (raw + 20480);
    float4* s_quad = (float4*)(raw + 30720);
    __shared__ int s_supcnt, s_cnt;
    __shared__ int s_qcnt[4];
    __shared__ int s_pixcnt[PIX];

    const uint32_t rank = cluster_rank();
    const int c  = blockIdx.x >> 3;     // cluster id: 4x2 tiles super-tile
    const int cx = c & 3;
    const int cy = c >> 2;
    const int tx = cx * 4 + (rank & 3);
    const int ty = cy * 2 + (int)(rank >> 2);
    const int tid = threadIdx.x;

    if (tid < PIX) s_pixcnt[tid] = 0;
    if (tid < 4)   s_qcnt[tid] = 0;
    if (tid == 0)  { s_supcnt = 0; s_cnt = 0; }
    __syncthreads();

    // ---- super-tile bbox (32x16 px) over pixel centers, padded (NDC) ----
    const float SEPS = 1e-4f;
    const float SX0 = ((float)(cx * 32)      + 0.5f) * (2.0f / W) - 1.0f - RADIUS - SEPS;
    const float SX1 = ((float)(cx * 32 + 31) + 0.5f) * (2.0f / W) - 1.0f + RADIUS + SEPS;
    const float SY0 = ((float)(cy * 16)      + 0.5f) * (2.0f / H) - 1.0f - RADIUS - SEPS;
    const float SY1 = ((float)(cy * 16 + 15) + 0.5f) * (2.0f / H) - 1.0f + RADIUS + SEPS;

    // ---- Phase 1: cull this CTA's 1/8 slice vs super-bbox (division-free) ----
    {
        const int slice = (n + CSIZE - 1) / CSIZE;
        const int i0 = (int)rank * slice;
        const int i1 = min(n, i0 + slice);
        for (int i = i0 + tid; i < i1; i += TPB) {
            float x = pts[3 * i + 0];
            float y = pts[3 * i + 1];
            float z = pts[3 * i + 2];
            bool hit = (z > 0.0f) &&
                       (x >= SX0 * z) && (x <= SX1 * z) &&
                       (y >= SY0 * z) && (y <= SY1 * z);
            if (hit) {
                float px = x / z;          // exact IEEE, matches reference
                float py = y / z;
                int slot = atomicAdd(&s_supcnt, 1);
                if (slot < SUPCAP)
                    s_sup[slot] = make_float4(px, py, z, __int_as_float(i));
            }
        }
    }
    __syncthreads();
    CLUSTER_ARRIVE(); CLUSTER_WAIT();      // pair 1: survivor lists visible

    // ---- Phase 2: gather cluster survivors, refine vs this tile's bbox ----
    const float EPS = 1e-5f;
    const float x0 = ((float)(tx * TILE)            + 0.5f) * (2.0f / W) - 1.0f - RADIUS - EPS;
    const float x1 = ((float)(tx * TILE + TILE - 1) + 0.5f) * (2.0f / W) - 1.0f + RADIUS + EPS;
    const float y0 = ((float)(ty * TILE)            + 0.5f) * (2.0f / H) - 1.0f - RADIUS - EPS;
    const float y1 = ((float)(ty * TILE + TILE - 1) + 0.5f) * (2.0f / H) - 1.0f + RADIUS + EPS;
    {
        const uint32_t supcnt_a = smem_u32(&s_supcnt);
        const uint32_t sup_a    = smem_u32(s_sup);
        int pc[CSIZE];
        #pragma unroll
        for (int q = 0; q < CSIZE; q++)
            pc[q] = min(ld_cluster_i32(mapa_u32(supcnt_a, q)), SUPCAP);
        #pragma unroll
        for (int q = 0; q < CSIZE; q++) {
            uint32_t base = mapa_u32(sup_a, q);
            for (int j = tid; j < pc[q]; j += TPB) {
                float4 r = ld_cluster_f4(base + j * 16u);
                if (r.x >= x0 && r.x <= x1 && r.y >= y0 && r.y <= y1) {
                    int slot = atomicAdd(&s_cnt, 1);
                    if (slot < CAPT) s_cand[slot] = r;
                }
            }
        }
    }
    __syncthreads();
    CLUSTER_ARRIVE();                      // pair 2 arrive (done reading peers)

    // ---- Phase 3: refine tile candidates into four 4x4-px quadrant lists ----
    const int cnt = min(s_cnt, CAPT);
    #pragma unroll
    for (int q = 0; q < 4; q++) {
        const float qx0 = ((float)(tx * TILE + (q & 1) * 4)     + 0.5f) * (2.0f / W) - 1.0f - RADIUS - EPS;
        const float qx1 = ((float)(tx * TILE + (q & 1) * 4 + 3) + 0.5f) * (2.0f / W) - 1.0f + RADIUS + EPS;
        const float qy0 = ((float)(ty * TILE + (q >> 1) * 4)     + 0.5f) * (2.0f / H) - 1.0f - RADIUS - EPS;
        const float qy1 = ((float)(ty * TILE + (q >> 1) * 4 + 3) + 0.5f) * (2.0f / H) - 1.0f + RADIUS + EPS;
        for (int j = tid; j < cnt; j += TPB) {
            float4 r = s_cand[j];
            if (r.x >= qx0 && r.x <= qx1 && r.y >= qy0 && r.y <= qy1) {
                int slot = atomicAdd(&s_qcnt[q], 1);
                if (slot < QCAP) s_quad[q * QCAP + slot] = r;
            }
        }
    }
    __syncthreads();
    CLUSTER_WAIT();   // pair 2 complete: peers done with our s_sup -> safe to alias

    // ---- Phase 4: scan quadrant list, push exact hits to per-pixel lists ----
    const int p = tid >> 3;                // pixel 0..63
    const int s = tid & 7;                 // sub-lane 0..7
    const int lx = p & (TILE - 1);
    const int ly = p >> 3;
    const int q  = ((ly >> 2) << 1) | (lx >> 2);
    const int ix = tx * TILE + lx;
    const int iy = ty * TILE + ly;
    const float gx = ((float)ix + 0.5f) * (2.0f / W) - 1.0f;
    const float gy = ((float)iy + 0.5f) * (2.0f / H) - 1.0f;
    const float r2 = RADIUS * RADIUS;
    {
        const int qc = min(s_qcnt[q], QCAP);
        for (int j = s; j < qc; j += SPLIT) {
            float4 cd = s_quad[q * QCAP + j];
            float dx = gx - cd.x;
            float dy = gy - cd.y;
            float d2 = dx * dx + dy * dy;
            if (d2 < r2) {                 // exact hit test (matches reference)
                int slot = atomicAdd(&s_pixcnt[p], 1);
                if (slot < PIXCAP) {
                    int o = p * PIXCAP + slot;
                    s_hz[o] = cd.z;
                    s_hd[o] = d2;
                    s_hi[o] = __float_as_int(cd.w);
                }
            }
        }
    }
    __syncthreads();

    // ---- Phase 5: per-pixel top-8 by depth + composite + store (tid<64) ----
    if (tid < PIX) {
        const int pp = tid;
        const int plx = pp & (TILE - 1);
        const int ply = pp >> 3;
        const int pix_x = tx * TILE + plx;
        const int pix_y = ty * TILE + ply;
        const int hc = min(s_pixcnt[pp], PIXCAP);

        float lz[K], ldd[K];
        int   li[K];
        #pragma unroll
        for (int k = 0; k < K; k++) { lz[k] = 3.0e38f; ldd[k] = 0.0f; li[k] = 0; }

        for (int j = 0; j < hc; j++) {
            int o = pp * PIXCAP + j;
            float z  = s_hz[o];
            // distinct depths -> top-K set is order-independent (matches top_k)
            if (z < lz[K - 1]) {
                lz[K - 1] = z; ldd[K - 1] = s_hd[o]; li[K - 1] = s_hi[o];
                #pragma unroll
                for (int k = K - 1; k > 0; k--) {
                    if (lz[k] < lz[k - 1]) {
                        float t0 = lz[k];  lz[k]  = lz[k - 1];  lz[k - 1]  = t0;
                        float t1 = ldd[k]; ldd[k] = ldd[k - 1]; ldd[k - 1] = t1;
                        int   t2 = li[k];  li[k]  = li[k - 1];  li[k - 1]  = t2;
                    }
                }
            }
        }

        // front-to-back weights, then batched feature gather (MLP 4 per round)
        float wk[K];
        int   idk[K];
        float T = 1.0f;
        const float inv_r2 = 1.0f / r2;
        #pragma unroll
        for (int k = 0; k < K; k++) {
            bool valid = lz[k] < 1.0e38f;
            float a = 1.0f - ldd[k] * inv_r2;
            a = fminf(fmaxf(a, 0.0f), 1.0f);
            a = valid ? a : 0.0f;
            wk[k]  = a * T;
            idk[k] = valid ? li[k] : 0;
            T *= (1.0f - a);
        }

        float acc[C];
        #pragma unroll
        for (int c2 = 0; c2 < C; c2++) acc[c2] = 0.0f;
        #pragma unroll
        for (int half = 0; half < 2; half++) {
            float4 F0[4], F1[4];
            #pragma unroll
            for (int k = 0; k < 4; k++) {
                const float4* f = (const float4*)(feat + (size_t)idk[half * 4 + k] * C);
                F0[k] = __ldg(&f[0]);
                F1[k] = __ldg(&f[1]);
            }
            #pragma unroll
            for (int k = 0; k < 4; k++) {
                float w = wk[half * 4 + k];
                acc[0] += w * F0[k].x; acc[1] += w * F0[k].y;
                acc[2] += w * F0[k].z; acc[3] += w * F0[k].w;
                acc[4] += w * F1[k].x; acc[5] += w * F1[k].y;
                acc[6] += w * F1[k].z; acc[7] += w * F1[k].w;
            }
        }

        float4* o = (float4*)(out + (size_t)(pix_y * W + pix_x) * C);
        o[0] = make_float4(acc[0], acc[1], acc[2], acc[3]);
        o[1] = make_float4(acc[4], acc[5], acc[6], acc[7]);
    }
}

extern "C" void kernel_launch(void* const* d_in, const int* in_sizes, int n_in,
                              void* d_out, int out_size) {
    const float* pts  = (const float*)d_in[0];   // [B,N,3] f32
    const float* feat = (const float*)d_in[1];   // [B,N,C] f32
    float* out = (float*)d_out;                  // [B,H,W,C] f32
    int n = in_sizes[0] / 3;                     // B=1 -> N
    if (n > MAXN) n = MAXN;

    render_kernel<<<NTILES, TPB>>>(pts, feat, out, n);
}

// round 10
// speedup vs baseline: 1.4510x; 1.1569x over previous
#include <cuda_runtime.h>
#include <cstdint>

// Problem constants (fixed by dataset): B=1, N=4096, C=8, H=W=128, K=8
#define MAXN 8192
constexpr float RADIUS = 0.05f;
constexpr int H = 128, W = 128, C = 8, K = 8;
constexpr int TILE = 8;             // 8x8 pixel tiles
constexpr int TX = W / TILE;        // 16
constexpr int TY = H / TILE;        // 16
constexpr int NTILES = TX * TY;     // 256 CTAs
constexpr int PIX = TILE * TILE;    // 64 pixels per tile
constexpr int SPLIT = 8;            // threads per pixel in scan phase
constexpr int TPB = PIX * SPLIT;    // 512 threads per CTA
constexpr int QCAP = 192;           // per-quadrant cap (mean ~27)
constexpr int PIXCAP = 40;          // per-pixel hit cap (mean ~8)

// smem: quadrant lists 4*192*16 = 12288 B; hit lists 64*40*12 = 30720 B -> 43008 B
constexpr int RAWSZ = 4 * QCAP * 16 + PIX * PIXCAP * 12;

__global__ void __launch_bounds__(TPB)
render_kernel(const float* __restrict__ pts,
              const float* __restrict__ feat,
              float* __restrict__ out, int n) {
    __shared__ __align__(16) unsigned char raw[RAWSZ];
    float4* s_quad = (float4*)raw;                                  // [4][QCAP]
    float*  s_hz   = (float*)(raw + 4 * QCAP * 16);                 // [64][40]
    float*  s_hd   = (float*)(raw + 4 * QCAP * 16 + PIX * PIXCAP * 4);
    int*    s_hi   = (int*)  (raw + 4 * QCAP * 16 + PIX * PIXCAP * 8);
    __shared__ int s_qcnt[4];
    __shared__ int s_pixcnt[PIX];

    const int tile = blockIdx.x;
    const int tx = tile & (TX - 1);
    const int ty = tile >> 4;
    const int tid = threadIdx.x;

    if (tid < PIX) s_pixcnt[tid] = 0;
    if (tid < 4)   s_qcnt[tid] = 0;
    __syncthreads();

    // ---- bboxes over pixel centers, expanded by splat radius + eps (NDC) ----
    const float EPS = 1e-5f;
    const float x0 = ((float)(tx * TILE)            + 0.5f) * (2.0f / W) - 1.0f - RADIUS - EPS;
    const float x1 = ((float)(tx * TILE + TILE - 1) + 0.5f) * (2.0f / W) - 1.0f + RADIUS + EPS;
    const float y0 = ((float)(ty * TILE)            + 0.5f) * (2.0f / H) - 1.0f - RADIUS - EPS;
    const float y1 = ((float)(ty * TILE + TILE - 1) + 0.5f) * (2.0f / H) - 1.0f + RADIUS + EPS;

    float qx0[2], qx1[2], qy0[2], qy1[2];
    #pragma unroll
    for (int h = 0; h < 2; h++) {
        qx0[h] = ((float)(tx * TILE + h * 4)     + 0.5f) * (2.0f / W) - 1.0f - RADIUS - EPS;
        qx1[h] = ((float)(tx * TILE + h * 4 + 3) + 0.5f) * (2.0f / W) - 1.0f + RADIUS + EPS;
        qy0[h] = ((float)(ty * TILE + h * 4)     + 0.5f) * (2.0f / H) - 1.0f - RADIUS - EPS;
        qy1[h] = ((float)(ty * TILE + h * 4 + 3) + 0.5f) * (2.0f / H) - 1.0f + RADIUS + EPS;
    }

    // ---- Phase 1: cull all points vs tile bbox (division-free), classify
    //      survivors straight into the four 4x4-px quadrant lists ----------
    #pragma unroll
    for (int it = 0; it < MAXN / TPB; it++) {
        int i = it * TPB + tid;
        if (i < n) {
            float x = pts[3 * i + 0];
            float y = pts[3 * i + 1];
            float z = pts[3 * i + 2];
            // z>0: x/z >= x0  <=>  x >= x0*z  (conservative; exact test later)
            bool hit = (z > 0.0f) &&
                       (x >= x0 * z) && (x <= x1 * z) &&
                       (y >= y0 * z) && (y <= y1 * z);
            if (hit) {
                float px = x / z;          // exact IEEE, matches reference
                float py = y / z;
                float4 rec = make_float4(px, py, z, __int_as_float(i));
                #pragma unroll
                for (int q = 0; q < 4; q++) {
                    if (px >= qx0[q & 1] && px <= qx1[q & 1] &&
                        py >= qy0[q >> 1] && py <= qy1[q >> 1]) {
                        int slot = atomicAdd(&s_qcnt[q], 1);
                        if (slot < QCAP) s_quad[q * QCAP + slot] = rec;
                    }
                }
            }
        }
    }
    __syncthreads();

    // ---- Phase 2: scan own quadrant list, push exact hits per pixel --------
    const int p = tid >> 3;                // pixel 0..63
    const int s = tid & 7;                 // sub-lane 0..7
    const int lx = p & (TILE - 1);
    const int ly = p >> 3;
    const int q  = ((ly >> 2) << 1) | (lx >> 2);
    const float gx = ((float)(tx * TILE + lx) + 0.5f) * (2.0f / W) - 1.0f;
    const float gy = ((float)(ty * TILE + ly) + 0.5f) * (2.0f / H) - 1.0f;
    const float r2 = RADIUS * RADIUS;
    {
        const int qc = min(s_qcnt[q], QCAP);
        for (int j = s; j < qc; j += SPLIT) {
            float4 cd = s_quad[q * QCAP + j];
            float dx = gx - cd.x;
            float dy = gy - cd.y;
            float d2 = dx * dx + dy * dy;
            if (d2 < r2) {                 // exact hit test (matches reference)
                int slot = atomicAdd(&s_pixcnt[p], 1);
                if (slot < PIXCAP) {
                    int o = p * PIXCAP + slot;
                    s_hz[o] = cd.z;
                    s_hd[o] = d2;
                    s_hi[o] = __float_as_int(cd.w);
                }
            }
        }
    }
    __syncthreads();

    // ---- Phase 3: per-pixel top-8 by depth + composite + store (tid<64) ----
    if (tid < PIX) {
        const int pp = tid;
        const int pix_x = tx * TILE + (pp & (TILE - 1));
        const int pix_y = ty * TILE + (pp >> 3);
        const int hc = min(s_pixcnt[pp], PIXCAP);

        float lz[K], ldd[K];
        int   li[K];
        #pragma unroll
        for (int k = 0; k < K; k++) { lz[k] = 3.0e38f; ldd[k] = 0.0f; li[k] = 0; }

        for (int j = 0; j < hc; j++) {
            int o = pp * PIXCAP + j;
            float z = s_hz[o];
            // distinct depths -> top-K set is order-independent (matches top_k)
            if (z < lz[K - 1]) {
                lz[K - 1] = z; ldd[K - 1] = s_hd[o]; li[K - 1] = s_hi[o];
                #pragma unroll
                for (int k = K - 1; k > 0; k--) {
                    if (lz[k] < lz[k - 1]) {
                        float t0 = lz[k];  lz[k]  = lz[k - 1];  lz[k - 1]  = t0;
                        float t1 = ldd[k]; ldd[k] = ldd[k - 1]; ldd[k - 1] = t1;
                        int   t2 = li[k];  li[k]  = li[k - 1];  li[k - 1]  = t2;
                    }
                }
            }
        }

        // front-to-back weights, then batched feature gather (MLP 4 per round)
        float wk[K];
        int   idk[K];
        float T = 1.0f;
        const float inv_r2 = 1.0f / r2;
        #pragma unroll
        for (int k = 0; k < K; k++) {
            bool valid = lz[k] < 1.0e38f;
            float a = 1.0f - ldd[k] * inv_r2;
            a = fminf(fmaxf(a, 0.0f), 1.0f);
            a = valid ? a : 0.0f;
            wk[k]  = a * T;
            idk[k] = valid ? li[k] : 0;
            T *= (1.0f - a);
        }

        float acc[C];
        #pragma unroll
        for (int c2 = 0; c2 < C; c2++) acc[c2] = 0.0f;
        #pragma unroll
        for (int half = 0; half < 2; half++) {
            float4 F0[4], F1[4];
            #pragma unroll
            for (int k = 0; k < 4; k++) {
                const float4* f = (const float4*)(feat + (size_t)idk[half * 4 + k] * C);
                F0[k] = __ldg(&f[0]);
                F1[k] = __ldg(&f[1]);
            }
            #pragma unroll
            for (int k = 0; k < 4; k++) {
                float w = wk[half * 4 + k];
                acc[0] += w * F0[k].x; acc[1] += w * F0[k].y;
                acc[2] += w * F0[k].z; acc[3] += w * F0[k].w;
                acc[4] += w * F1[k].x; acc[5] += w * F1[k].y;
                acc[6] += w * F1[k].z; acc[7] += w * F1[k].w;
            }
        }

        float4* o = (float4*)(out + (size_t)(pix_y * W + pix_x) * C);
        o[0] = make_float4(acc[0], acc[1], acc[2], acc[3]);
        o[1] = make_float4(acc[4], acc[5], acc[6], acc[7]);
    }
}

extern "C" void kernel_launch(void* const* d_in, const int* in_sizes, int n_in,
                              void* d_out, int out_size) {
    const float* pts  = (const float*)d_in[0];   // [B,N,3] f32
    const float* feat = (const float*)d_in[1];   // [B,N,C] f32
    float* out = (float*)d_out;                  // [B,H,W,C] f32
    int n = in_sizes[0] / 3;                     // B=1 -> N
    if (n > MAXN) n = MAXN;

    render_kernel<<<NTILES, TPB>>>(pts, feat, out, n);
}